// round 1
// baseline (speedup 1.0000x reference)
#include <cuda_runtime.h>
#include <math.h>

// Problem constants
constexpr int B  = 4;
constexpr int T  = 2048;
constexpr int D  = 768;
constexpr int H  = 12;
constexpr int HD = 64;
constexpr int BT = B * T;          // 8192
constexpr int NQKV = 3 * D;        // 2304
constexpr float EPS  = 1e-4f;
constexpr float GAIN = 1.8402f;

// Scratch (allocation-free rule: __device__ globals)
__device__ float g_wn_qkv[NQKV * D];       // normalized qkv weights (2304 x 768)
__device__ float g_wn_out[D * D];          // normalized out weights (768 x 768)
__device__ float g_Q[B * H * T * HD];      // normalized Q, [b][h][t][d]
__device__ float g_K[B * H * T * HD];      // normalized K
__device__ float g_V[B * H * T * HD];      // V
__device__ float g_att[BT * D];            // attention output in (B,T,D) layout
__device__ float g_mag[BT];                // per-token magnitude of x

__device__ __forceinline__ void fma44(float acc[4][4], float4 a, float4 b) {
    acc[0][0] += a.x * b.x; acc[0][1] += a.x * b.y; acc[0][2] += a.x * b.z; acc[0][3] += a.x * b.w;
    acc[1][0] += a.y * b.x; acc[1][1] += a.y * b.y; acc[1][2] += a.y * b.z; acc[1][3] += a.y * b.w;
    acc[2][0] += a.z * b.x; acc[2][1] += a.z * b.y; acc[2][2] += a.z * b.z; acc[2][3] += a.z * b.w;
    acc[3][0] += a.w * b.x; acc[3][1] += a.w * b.y; acc[3][2] += a.w * b.z; acc[3][3] += a.w * b.w;
}

// ---------------------------------------------------------------------------
// Kernel 1: weight row-normalization (qkv_w, out_w) + per-token x magnitude.
// One block per 768-length vector. blocks [0,2304): qkv rows; [2304,3072): out
// rows; [3072, 3072+8192): x token rows -> mag.
// ---------------------------------------------------------------------------
__global__ void __launch_bounds__(256) prep_kernel(const float* __restrict__ x,
                                                   const float* __restrict__ qkv_w,
                                                   const float* __restrict__ out_w) {
    const int r = blockIdx.x;
    const float* src;
    float* dst = nullptr;
    float* magdst = nullptr;
    if (r < NQKV) {
        src = qkv_w + (size_t)r * D;
        dst = g_wn_qkv + (size_t)r * D;
    } else if (r < NQKV + D) {
        src = out_w + (size_t)(r - NQKV) * D;
        dst = g_wn_out + (size_t)(r - NQKV) * D;
    } else {
        src = x + (size_t)(r - (NQKV + D)) * D;
        magdst = g_mag + (r - (NQKV + D));
    }
    const int tid = threadIdx.x;
    float v[3];
    float s = 0.f;
#pragma unroll
    for (int i = 0; i < 3; i++) {
        v[i] = src[tid + i * 256];
        s += v[i] * v[i];
    }
#pragma unroll
    for (int o = 16; o > 0; o >>= 1) s += __shfl_xor_sync(0xffffffffu, s, o);
    __shared__ float red[8];
    __shared__ float stot;
    if ((tid & 31) == 0) red[tid >> 5] = s;
    __syncthreads();
    if (tid == 0) {
        float t = red[0];
#pragma unroll
        for (int i = 1; i < 8; i++) t += red[i];
        stot = t;
    }
    __syncthreads();
    const float tot = stot;
    if (dst) {
        const float inv = 1.0f / (sqrtf(tot) + EPS);
#pragma unroll
        for (int i = 0; i < 3; i++) dst[tid + i * 256] = v[i] * inv;
    } else if (tid == 0) {
        magdst[0] = sqrtf(tot) * (1.0f / sqrtf((float)D));
    }
}

// ---------------------------------------------------------------------------
// Kernel 2: qkv = x @ wn^T, scattered to Q/K/V [b][h][t][d], with fused
// per-head RMS normalize for Q and K (the 64-wide n-tile == one head).
// 64x64 tile, 256 threads, 4x4 microtiles, K-tile = 16.
// grid: (2304/64, 8192/64)
// ---------------------------------------------------------------------------
__global__ void __launch_bounds__(256) qkv_gemm_kernel(const float* __restrict__ x) {
    __shared__ __align__(16) float Xs[16][68];
    __shared__ __align__(16) float Ws[16][68];
    const int n0 = blockIdx.x * 64;
    const int m0 = blockIdx.y * 64;
    const int tid = threadIdx.x;
    const int tx = tid & 15, ty = tid >> 4;
    const float* A = x + (size_t)m0 * D;
    const float* W = g_wn_qkv + (size_t)n0 * D;
    float acc[4][4] = {};
    for (int k0 = 0; k0 < D; k0 += 16) {
#pragma unroll
        for (int l = tid; l < 1024; l += 256) {
            const int r = l >> 4, c = l & 15;
            Xs[c][r] = A[(size_t)r * D + k0 + c];
            Ws[c][r] = W[(size_t)r * D + k0 + c];
        }
        __syncthreads();
#pragma unroll
        for (int k = 0; k < 16; k++) {
            const float4 a = *(const float4*)&Xs[k][ty * 4];
            const float4 b = *(const float4*)&Ws[k][tx * 4];
            fma44(acc, a, b);
        }
        __syncthreads();
    }
    const int which = n0 / D;            // 0=q 1=k 2=v
    const int h = (n0 % D) / HD;
    const int b = m0 / T;
    float* dstbase = (which == 0) ? g_Q : (which == 1) ? g_K : g_V;
#pragma unroll
    for (int i = 0; i < 4; i++) {
        if (which < 2) {
            float s = 0.f;
#pragma unroll
            for (int j = 0; j < 4; j++) s += acc[i][j] * acc[i][j];
            // reduce across the 16 tx lanes (lane bits 0..3)
#pragma unroll
            for (int o = 1; o < 16; o <<= 1) s += __shfl_xor_sync(0xffffffffu, s, o);
            const float sc = 8.0f / (sqrtf(s) + EPS);   // sqrt(HD)=8
#pragma unroll
            for (int j = 0; j < 4; j++) acc[i][j] *= sc;
        }
        const int m = m0 + ty * 4 + i;
        const int t = m & (T - 1);
        float4* dp = (float4*)(dstbase + (((size_t)(b * H + h)) * T + t) * HD + tx * 4);
        *dp = make_float4(acc[i][0], acc[i][1], acc[i][2], acc[i][3]);
    }
}

// ---------------------------------------------------------------------------
// Kernel 3: fused sigmoid attention per (b,h): O = sigma(Q K^T / 8) V, then
// per-token normalize * mag. Block = 64 query rows x full HD=64.
// grid: (T/64, H, B), 256 threads, dynamic smem = 4 * 64*68 floats = 69632 B.
// ---------------------------------------------------------------------------
constexpr int SPAD = 68;
constexpr int ATTN_SMEM = 4 * 64 * SPAD * (int)sizeof(float);

__global__ void __launch_bounds__(256) attn_kernel() {
    extern __shared__ __align__(16) float sm[];
    float* Qst = sm;                 // [d][t]  (transposed)
    float* Kst = sm + 64 * SPAD;     // [d][s]  (transposed)
    float* Vs  = sm + 2 * 64 * SPAD; // [s][d]
    float* Ps  = sm + 3 * 64 * SPAD; // [t][s]
    const int tid = threadIdx.x;
    const int tx = tid & 15, ty = tid >> 4;
    const int tq0 = blockIdx.x * 64;
    const int h = blockIdx.y, b = blockIdx.z;
    const size_t bh = ((size_t)(b * H + h)) * T;

    const float* Qg = g_Q + (bh + tq0) * HD;
    for (int l = tid; l < 4096; l += 256) {
        const int r = l >> 6, d = l & 63;
        Qst[d * SPAD + r] = Qg[r * HD + d];
    }

    float acc[4][4] = {};
    for (int s0 = 0; s0 < T; s0 += 64) {
        const float* Kg = g_K + (bh + s0) * HD;
        const float* Vg = g_V + (bh + s0) * HD;
        __syncthreads();   // previous iter readers of Kst/Vs/Ps done (also guards Q on iter 0 via next sync)
        for (int l = tid; l < 4096; l += 256) {
            const int r = l >> 6, d = l & 63;
            Kst[d * SPAD + r] = Kg[r * HD + d];
            Vs[r * SPAD + d]  = Vg[r * HD + d];
        }
        __syncthreads();
        // S = Q K^T (64x64x64)
        float p[4][4] = {};
#pragma unroll 8
        for (int d = 0; d < 64; d++) {
            const float4 a  = *(const float4*)&Qst[d * SPAD + ty * 4];
            const float4 bb = *(const float4*)&Kst[d * SPAD + tx * 4];
            fma44(p, a, bb);
        }
        // sigmoid(s/8) and stage P
#pragma unroll
        for (int i = 0; i < 4; i++) {
#pragma unroll
            for (int j = 0; j < 4; j++)
                p[i][j] = 1.0f / (1.0f + __expf(-0.125f * p[i][j]));
            *(float4*)&Ps[(ty * 4 + i) * SPAD + tx * 4] =
                make_float4(p[i][0], p[i][1], p[i][2], p[i][3]);
        }
        __syncthreads();
        // O += P V (64x64x64)
#pragma unroll 8
        for (int jj = 0; jj < 64; jj++) {
            const float4 bb = *(const float4*)&Vs[jj * SPAD + tx * 4];
            const float a0 = Ps[(ty * 4 + 0) * SPAD + jj];
            const float a1 = Ps[(ty * 4 + 1) * SPAD + jj];
            const float a2 = Ps[(ty * 4 + 2) * SPAD + jj];
            const float a3 = Ps[(ty * 4 + 3) * SPAD + jj];
            fma44(acc, make_float4(a0, a1, a2, a3), bb);
        }
    }
    // Epilogue: o = c*acc; out = mag * 8 * o / (||o|| + eps)
    const float c = GAIN / sqrtf((float)T);
#pragma unroll
    for (int i = 0; i < 4; i++) {
        float s = 0.f;
#pragma unroll
        for (int j = 0; j < 4; j++) s += acc[i][j] * acc[i][j];
#pragma unroll
        for (int o = 1; o < 16; o <<= 1) s += __shfl_xor_sync(0xffffffffu, s, o);
        const int t = tq0 + ty * 4 + i;
        const float n = c * sqrtf(s);
        const float f = 8.0f * c * g_mag[b * T + t] / (n + EPS);
        float4* dp = (float4*)(g_att + ((size_t)b * T + t) * D + h * HD + tx * 4);
        *dp = make_float4(acc[i][0] * f, acc[i][1] * f, acc[i][2] * f, acc[i][3] * f);
    }
}

// ---------------------------------------------------------------------------
// Kernel 4: y = att @ wn_out^T   (8192 x 768 x 768)
// grid: (768/64, 8192/64)
// ---------------------------------------------------------------------------
__global__ void __launch_bounds__(256) proj_gemm_kernel(float* __restrict__ out) {
    __shared__ __align__(16) float As[16][68];
    __shared__ __align__(16) float Ws[16][68];
    const int n0 = blockIdx.x * 64;
    const int m0 = blockIdx.y * 64;
    const int tid = threadIdx.x;
    const int tx = tid & 15, ty = tid >> 4;
    const float* A = g_att + (size_t)m0 * D;
    const float* W = g_wn_out + (size_t)n0 * D;
    float acc[4][4] = {};
    for (int k0 = 0; k0 < D; k0 += 16) {
#pragma unroll
        for (int l = tid; l < 1024; l += 256) {
            const int r = l >> 4, c = l & 15;
            As[c][r] = A[(size_t)r * D + k0 + c];
            Ws[c][r] = W[(size_t)r * D + k0 + c];
        }
        __syncthreads();
#pragma unroll
        for (int k = 0; k < 16; k++) {
            const float4 a = *(const float4*)&As[k][ty * 4];
            const float4 b = *(const float4*)&Ws[k][tx * 4];
            fma44(acc, a, b);
        }
        __syncthreads();
    }
#pragma unroll
    for (int i = 0; i < 4; i++) {
        const int m = m0 + ty * 4 + i;
        float4* dp = (float4*)(out + (size_t)m * D + n0 + tx * 4);
        *dp = make_float4(acc[i][0], acc[i][1], acc[i][2], acc[i][3]);
    }
}

// ---------------------------------------------------------------------------
extern "C" void kernel_launch(void* const* d_in, const int* in_sizes, int n_in,
                              void* d_out, int out_size) {
    const float* x     = (const float*)d_in[0];
    const float* qkv_w = (const float*)d_in[1];
    const float* out_w = (const float*)d_in[2];

    prep_kernel<<<NQKV + D + BT, 256>>>(x, qkv_w, out_w);
    qkv_gemm_kernel<<<dim3(NQKV / 64, BT / 64), 256>>>(x);
    cudaFuncSetAttribute(attn_kernel, cudaFuncAttributeMaxDynamicSharedMemorySize,
                         ATTN_SMEM);
    attn_kernel<<<dim3(T / 64, H, B), 256, ATTN_SMEM>>>();
    proj_gemm_kernel<<<dim3(D / 64, BT / 64), 256>>>((float*)d_out);
}

// round 3
// speedup vs baseline: 2.8123x; 2.8123x over previous
#include <cuda_runtime.h>
#include <math.h>
#include <stdint.h>

// Problem constants
constexpr int B  = 4;
constexpr int T  = 2048;
constexpr int D  = 768;
constexpr int H  = 12;
constexpr int HD = 64;
constexpr int BT = B * T;          // 8192
constexpr int NQKV = 3 * D;        // 2304
constexpr float EPS  = 1e-4f;
constexpr float GAIN = 1.8402f;

constexpr int PAD  = 36;           // GEMM k-chunk stride: (4g+c) mod 32 unique
constexpr int APAD = 68;           // attention 64-wide tile stride (4 mod 32)
constexpr int KC  = 32;            // GEMM k-chunk

// Scratch (allocation-free rule: __device__ globals)
__device__ float g_wn_qkv[NQKV * D];
__device__ float g_wn_out[D * D];
__device__ float g_Q[B * H * T * HD];
__device__ float g_K[B * H * T * HD];
__device__ float g_V[B * H * T * HD];
__device__ float g_att[BT * D];
__device__ float g_mag[BT];

__device__ __forceinline__ uint32_t tf32(float x) {
    uint32_t u; asm("cvt.rna.tf32.f32 %0, %1;" : "=r"(u) : "f"(x)); return u;
}

__device__ __forceinline__ void mma8(float c[4], const uint32_t a[4], const uint32_t b[2]) {
    asm volatile(
        "mma.sync.aligned.m16n8k8.row.col.f32.tf32.tf32.f32 "
        "{%0,%1,%2,%3}, {%4,%5,%6,%7}, {%8,%9}, {%0,%1,%2,%3};"
        : "+f"(c[0]), "+f"(c[1]), "+f"(c[2]), "+f"(c[3])
        : "r"(a[0]), "r"(a[1]), "r"(a[2]), "r"(a[3]), "r"(b[0]), "r"(b[1]));
}

// ---------------------------------------------------------------------------
// Kernel 1: weight row-normalization + per-token x magnitude.
// ---------------------------------------------------------------------------
__global__ void __launch_bounds__(256) prep_kernel(const float* __restrict__ x,
                                                   const float* __restrict__ qkv_w,
                                                   const float* __restrict__ out_w) {
    const int r = blockIdx.x;
    const float* src;
    float* dst = nullptr;
    float* magdst = nullptr;
    if (r < NQKV) {
        src = qkv_w + (size_t)r * D;
        dst = g_wn_qkv + (size_t)r * D;
    } else if (r < NQKV + D) {
        src = out_w + (size_t)(r - NQKV) * D;
        dst = g_wn_out + (size_t)(r - NQKV) * D;
    } else {
        src = x + (size_t)(r - (NQKV + D)) * D;
        magdst = g_mag + (r - (NQKV + D));
    }
    const int tid = threadIdx.x;
    float v[3];
    float s = 0.f;
#pragma unroll
    for (int i = 0; i < 3; i++) { v[i] = src[tid + i * 256]; s += v[i] * v[i]; }
#pragma unroll
    for (int o = 16; o > 0; o >>= 1) s += __shfl_xor_sync(0xffffffffu, s, o);
    __shared__ float red[8];
    __shared__ float stot;
    if ((tid & 31) == 0) red[tid >> 5] = s;
    __syncthreads();
    if (tid == 0) {
        float t = red[0];
#pragma unroll
        for (int i = 1; i < 8; i++) t += red[i];
        stot = t;
    }
    __syncthreads();
    const float tot = stot;
    if (dst) {
        const float inv = 1.0f / (sqrtf(tot) + EPS);
#pragma unroll
        for (int i = 0; i < 3; i++) dst[tid + i * 256] = v[i] * inv;
    } else if (tid == 0) {
        magdst[0] = sqrtf(tot) * (1.0f / sqrtf((float)D));
    }
}

// ---------------------------------------------------------------------------
// tf32 GEMM core: C[128 x 64] += A[m0..][0..768] * W[n0..][0..768]^T
// 256 threads = 8 warps (4m x 2n), warp tile 32x32 (2 mtiles x 4 ntiles).
// SMEM tiles pre-converted to tf32, PAD=36 -> conflict-free fragment loads.
// Register double-buffered global prefetch.
// ---------------------------------------------------------------------------
__device__ __forceinline__ void gemm_core(const float* __restrict__ A,
                                          const float* __restrict__ W,
                                          int m0, int n0,
                                          uint32_t* As, uint32_t* Bs,
                                          float (&acc)[2][4][4], int tid) {
    const int lane = tid & 31, warp = tid >> 5;
    const int wm = warp >> 1, wn = warp & 1;
    const int g = lane >> 2, c = lane & 3;
    const float* Ab = A + (size_t)m0 * D;
    const float* Wb = W + (size_t)n0 * D;

    float4 pa[4], pb[2];
#pragma unroll
    for (int i = 0; i < 4; i++) {
        int l = tid + i * 256, r = l >> 3, cc = (l & 7) * 4;
        pa[i] = *(const float4*)&Ab[(size_t)r * D + cc];
    }
#pragma unroll
    for (int i = 0; i < 2; i++) {
        int l = tid + i * 256, r = l >> 3, cc = (l & 7) * 4;
        pb[i] = *(const float4*)&Wb[(size_t)r * D + cc];
    }

    for (int k0 = 0; k0 < D; k0 += KC) {
        if (k0) __syncthreads();
#pragma unroll
        for (int i = 0; i < 4; i++) {
            int l = tid + i * 256, r = l >> 3, cc = (l & 7) * 4;
            uint32_t* p = &As[r * PAD + cc];
            p[0] = tf32(pa[i].x); p[1] = tf32(pa[i].y);
            p[2] = tf32(pa[i].z); p[3] = tf32(pa[i].w);
        }
#pragma unroll
        for (int i = 0; i < 2; i++) {
            int l = tid + i * 256, r = l >> 3, cc = (l & 7) * 4;
            uint32_t* p = &Bs[r * PAD + cc];
            p[0] = tf32(pb[i].x); p[1] = tf32(pb[i].y);
            p[2] = tf32(pb[i].z); p[3] = tf32(pb[i].w);
        }
        __syncthreads();
        if (k0 + KC < D) {
#pragma unroll
            for (int i = 0; i < 4; i++) {
                int l = tid + i * 256, r = l >> 3, cc = (l & 7) * 4;
                pa[i] = *(const float4*)&Ab[(size_t)r * D + k0 + KC + cc];
            }
#pragma unroll
            for (int i = 0; i < 2; i++) {
                int l = tid + i * 256, r = l >> 3, cc = (l & 7) * 4;
                pb[i] = *(const float4*)&Wb[(size_t)r * D + k0 + KC + cc];
            }
        }
#pragma unroll
        for (int ks = 0; ks < 4; ks++) {
            const int kk = ks * 8;
            uint32_t af[2][4], bf[4][2];
#pragma unroll
            for (int mt = 0; mt < 2; mt++) {
                const uint32_t* p = &As[(wm * 32 + mt * 16 + g) * PAD + kk + c];
                af[mt][0] = p[0];        af[mt][2] = p[4];
                af[mt][1] = p[8 * PAD];  af[mt][3] = p[8 * PAD + 4];
            }
#pragma unroll
            for (int nt = 0; nt < 4; nt++) {
                const uint32_t* p = &Bs[(wn * 32 + nt * 8 + g) * PAD + kk + c];
                bf[nt][0] = p[0]; bf[nt][1] = p[4];
            }
#pragma unroll
            for (int mt = 0; mt < 2; mt++)
#pragma unroll
                for (int nt = 0; nt < 4; nt++) mma8(acc[mt][nt], af[mt], bf[nt]);
        }
    }
}

// ---------------------------------------------------------------------------
// Kernel 2: qkv GEMM + fused per-head q/k RMS-normalize + scatter to Q/K/V.
// grid: (2304/64, 8192/128)
// ---------------------------------------------------------------------------
__global__ void __launch_bounds__(256) qkv_mm(const float* __restrict__ x) {
    __shared__ uint32_t As[128 * PAD];
    __shared__ uint32_t Bs[64 * PAD];
    __shared__ float part[2][128];
    const int n0 = blockIdx.x * 64, m0 = blockIdx.y * 128;
    const int tid = threadIdx.x, lane = tid & 31, warp = tid >> 5;
    const int wm = warp >> 1, wn = warp & 1, g = lane >> 2, c = lane & 3;

    float acc[2][4][4] = {};
    gemm_core(x, g_wn_qkv, m0, n0, As, Bs, acc, tid);

    const int which = n0 / D;                 // 0=q 1=k 2=v (block n-extent == one head)
    const int h = (n0 % D) / HD;
    const int b = m0 / T;
    float* dstb = (which == 0) ? g_Q : (which == 1) ? g_K : g_V;

    if (which < 2) {
#pragma unroll
        for (int mt = 0; mt < 2; mt++) {
            float s0 = 0.f, s1 = 0.f;
#pragma unroll
            for (int nt = 0; nt < 4; nt++) {
                s0 += acc[mt][nt][0] * acc[mt][nt][0] + acc[mt][nt][1] * acc[mt][nt][1];
                s1 += acc[mt][nt][2] * acc[mt][nt][2] + acc[mt][nt][3] * acc[mt][nt][3];
            }
            s0 += __shfl_xor_sync(~0u, s0, 1); s0 += __shfl_xor_sync(~0u, s0, 2);
            s1 += __shfl_xor_sync(~0u, s1, 1); s1 += __shfl_xor_sync(~0u, s1, 2);
            if (c == 0) {
                part[wn][wm * 32 + mt * 16 + g]     = s0;
                part[wn][wm * 32 + mt * 16 + g + 8] = s1;
            }
        }
        __syncthreads();
    }
#pragma unroll
    for (int mt = 0; mt < 2; mt++) {
#pragma unroll
        for (int rr = 0; rr < 2; rr++) {
            const int ml = wm * 32 + mt * 16 + g + rr * 8;
            const int m  = m0 + ml;
            const int t  = m & (T - 1);
            float sc = 1.f;
            if (which < 2) {
                const float ss = part[0][ml] + part[1][ml];
                sc = 8.0f / (sqrtf(ss) + EPS);           // sqrt(HD)=8
            }
            float* dp = dstb + (((size_t)(b * H + h)) * T + t) * HD;
#pragma unroll
            for (int nt = 0; nt < 4; nt++) {
                const int col = wn * 32 + nt * 8 + 2 * c;
                *(float2*)&dp[col] = make_float2(acc[mt][nt][rr * 2] * sc,
                                                 acc[mt][nt][rr * 2 + 1] * sc);
            }
        }
    }
}

// ---------------------------------------------------------------------------
// Kernel 3: fused sigmoid attention with tf32 mma.
// Block: 128 q-rows, 8 warps (16 rows x 64 cols each). Q frags in registers.
// S C-frag -> PV A-frag via warp shuffles (no SMEM round-trip for P).
// K/V tiles use APAD=68 stride (64-wide rows!).
// grid: (T/128, H, B)
// ---------------------------------------------------------------------------
__global__ void __launch_bounds__(256) attn_mma() {
    __shared__ uint32_t Ks[64 * APAD];
    __shared__ uint32_t Vs[64 * APAD];
    const int tid = threadIdx.x, lane = tid & 31, warp = tid >> 5;
    const int g = lane >> 2, c = lane & 3;
    const int q0 = blockIdx.x * 128;
    const int h = blockIdx.y, b = blockIdx.z;
    const size_t bh = ((size_t)(b * H + h)) * T;

    // Q fragments (16 rows x 64 k), persistent in registers
    uint32_t qf[8][4];
    {
        const float* Qg = g_Q + (bh + q0 + warp * 16) * HD;
#pragma unroll
        for (int kt = 0; kt < 8; kt++) {
            qf[kt][0] = tf32(Qg[(size_t)g * HD + kt * 8 + c]);
            qf[kt][1] = tf32(Qg[(size_t)(g + 8) * HD + kt * 8 + c]);
            qf[kt][2] = tf32(Qg[(size_t)g * HD + kt * 8 + c + 4]);
            qf[kt][3] = tf32(Qg[(size_t)(g + 8) * HD + kt * 8 + c + 4]);
        }
    }

    float oacc[8][4] = {};
    const int src0 = (lane & 28) | (c >> 1);
    const int src1 = src0 + 2;
    const bool odd = c & 1;

    for (int s0 = 0; s0 < T; s0 += 64) {
        __syncthreads();
        const float* Kg = g_K + (bh + s0) * HD;
        const float* Vg = g_V + (bh + s0) * HD;
#pragma unroll
        for (int i = 0; i < 4; i++) {
            int l = tid + i * 256, r = l >> 4, cc = (l & 15) * 4;
            float4 kv = *(const float4*)&Kg[(size_t)r * HD + cc];
            float4 vv = *(const float4*)&Vg[(size_t)r * HD + cc];
            uint32_t* kp = &Ks[r * APAD + cc];
            kp[0] = tf32(kv.x); kp[1] = tf32(kv.y); kp[2] = tf32(kv.z); kp[3] = tf32(kv.w);
            uint32_t* vp = &Vs[r * APAD + cc];
            vp[0] = tf32(vv.x); vp[1] = tf32(vv.y); vp[2] = tf32(vv.z); vp[3] = tf32(vv.w);
        }
        __syncthreads();

        // S = Q K^T  (16 x 64 per warp)
        float sacc[8][4] = {};
#pragma unroll
        for (int ks = 0; ks < 8; ks++) {
            uint32_t bf[8][2];
#pragma unroll
            for (int nt = 0; nt < 8; nt++) {
                const uint32_t* p = &Ks[(nt * 8 + g) * APAD + ks * 8 + c];
                bf[nt][0] = p[0]; bf[nt][1] = p[4];
            }
#pragma unroll
            for (int nt = 0; nt < 8; nt++) mma8(sacc[nt], qf[ks], bf[nt]);
        }

        // sigmoid(S/8)
#pragma unroll
        for (int nt = 0; nt < 8; nt++)
#pragma unroll
            for (int j = 0; j < 4; j++)
                sacc[nt][j] = 1.0f / (1.0f + __expf(-0.125f * sacc[nt][j]));

        // O += P V  (C-frag -> A-frag via shuffles)
#pragma unroll
        for (int kt = 0; kt < 8; kt++) {
            uint32_t af[4];
            float w0 = __shfl_sync(~0u, sacc[kt][0], src0);
            float w1 = __shfl_sync(~0u, sacc[kt][1], src0);
            af[0] = tf32(odd ? w1 : w0);
            float w2 = __shfl_sync(~0u, sacc[kt][2], src0);
            float w3 = __shfl_sync(~0u, sacc[kt][3], src0);
            af[1] = tf32(odd ? w3 : w2);
            float x0 = __shfl_sync(~0u, sacc[kt][0], src1);
            float x1 = __shfl_sync(~0u, sacc[kt][1], src1);
            af[2] = tf32(odd ? x1 : x0);
            float x2 = __shfl_sync(~0u, sacc[kt][2], src1);
            float x3 = __shfl_sync(~0u, sacc[kt][3], src1);
            af[3] = tf32(odd ? x3 : x2);
#pragma unroll
            for (int nt = 0; nt < 8; nt++) {
                uint32_t bf2[2];
                const uint32_t* vp = &Vs[(kt * 8 + c) * APAD + nt * 8 + g];
                bf2[0] = vp[0]; bf2[1] = vp[4 * APAD];
                mma8(oacc[nt], af, bf2);
            }
        }
    }

    // Epilogue: o = cst*acc; out = mag * 8*cst*acc / (cst*||acc|| + eps)
    const float cst = GAIN * rsqrtf((float)T);
#pragma unroll
    for (int rr = 0; rr < 2; rr++) {
        float s = 0.f;
#pragma unroll
        for (int nt = 0; nt < 8; nt++)
            s += oacc[nt][rr * 2] * oacc[nt][rr * 2] + oacc[nt][rr * 2 + 1] * oacc[nt][rr * 2 + 1];
        s += __shfl_xor_sync(~0u, s, 1);
        s += __shfl_xor_sync(~0u, s, 2);
        const int t = q0 + warp * 16 + g + rr * 8;
        const float n = cst * sqrtf(s);
        const float f = 8.0f * cst * g_mag[b * T + t] / (n + EPS);
        float* dp = g_att + ((size_t)b * T + t) * D + h * HD;
#pragma unroll
        for (int nt = 0; nt < 8; nt++)
            *(float2*)&dp[nt * 8 + 2 * c] = make_float2(oacc[nt][rr * 2] * f,
                                                        oacc[nt][rr * 2 + 1] * f);
    }
}

// ---------------------------------------------------------------------------
// Kernel 4: out-projection  y = att @ wn_out^T
// grid: (768/64, 8192/128)
// ---------------------------------------------------------------------------
__global__ void __launch_bounds__(256) proj_mm(float* __restrict__ out) {
    __shared__ uint32_t As[128 * PAD];
    __shared__ uint32_t Bs[64 * PAD];
    const int n0 = blockIdx.x * 64, m0 = blockIdx.y * 128;
    const int tid = threadIdx.x, lane = tid & 31, warp = tid >> 5;
    const int wm = warp >> 1, wn = warp & 1, g = lane >> 2, c = lane & 3;

    float acc[2][4][4] = {};
    gemm_core(g_att, g_wn_out, m0, n0, As, Bs, acc, tid);

#pragma unroll
    for (int mt = 0; mt < 2; mt++) {
#pragma unroll
        for (int rr = 0; rr < 2; rr++) {
            const int m = m0 + wm * 32 + mt * 16 + g + rr * 8;
            float* dp = out + (size_t)m * D + n0;
#pragma unroll
            for (int nt = 0; nt < 4; nt++) {
                const int col = wn * 32 + nt * 8 + 2 * c;
                *(float2*)&dp[col] = make_float2(acc[mt][nt][rr * 2],
                                                 acc[mt][nt][rr * 2 + 1]);
            }
        }
    }
}

// ---------------------------------------------------------------------------
extern "C" void kernel_launch(void* const* d_in, const int* in_sizes, int n_in,
                              void* d_out, int out_size) {
    const float* x     = (const float*)d_in[0];
    const float* qkv_w = (const float*)d_in[1];
    const float* out_w = (const float*)d_in[2];

    prep_kernel<<<NQKV + D + BT, 256>>>(x, qkv_w, out_w);
    qkv_mm<<<dim3(NQKV / 64, BT / 128), 256>>>(x);
    attn_mma<<<dim3(T / 128, H, B), 256>>>();
    proj_mm<<<dim3(D / 64, BT / 128), 256>>>((float*)d_out);
}